// round 4
// baseline (speedup 1.0000x reference)
#include <cuda_runtime.h>
#include <cuda_fp16.h>
#include <cstdint>

#define N_NODES 50000
#define N_EDGES 1600000
#define D_FEAT  128
#define NV4     (D_FEAT / 4)   // 32 float4 per fp32 row
#define NH2     (D_FEAT / 4)   // 32 uint2 (4 halfs) per fp16 row

#define SCAN_CHUNK   1024
#define SCAN_BLOCKS  ((N_NODES + SCAN_CHUNK - 1) / SCAN_CHUNK)   // 49

// Scratch (no cudaMalloc allowed).
__device__ uint2 g_xh      [(size_t)N_NODES * NH2];   // fp16 copy of gather operand
__device__ uint2 g_scratchh[(size_t)N_NODES * NH2];   // fp16 round-1 result
__device__ int   g_counts  [N_NODES];
__device__ int   g_row_ptr [N_NODES + 1];
__device__ int   g_eoff    [N_EDGES];
__device__ int2  g_edges   [N_EDGES];                 // packed (col, val-bits)
__device__ int   g_partials[SCAN_BLOCKS];
__device__ int   g_poffs   [SCAN_BLOCKS];

// ---------------- fp32 -> fp16 conversion (4 feats / thread) ----------------
__global__ void conv_kernel(const float4* __restrict__ in, uint2* __restrict__ out, int n) {
    int i = blockIdx.x * blockDim.x + threadIdx.x;
    if (i >= n) return;
    float4 f = in[i];
    __half2 h0 = __float22half2_rn(make_float2(f.x, f.y));
    __half2 h1 = __float22half2_rn(make_float2(f.z, f.w));
    uint2 o;
    o.x = *reinterpret_cast<unsigned*>(&h0);
    o.y = *reinterpret_cast<unsigned*>(&h1);
    out[i] = o;
}

// ---------------- CSR build ----------------
__global__ void zero_counts_kernel(int* __restrict__ counts) {
    int i = blockIdx.x * blockDim.x + threadIdx.x;
    if (i < N_NODES) counts[i] = 0;
}

// Histogram + record each edge's rank within its row.
__global__ void hist_kernel(const int* __restrict__ adj_row, int* __restrict__ counts,
                            int* __restrict__ eoff, int n_edges) {
    int e = blockIdx.x * blockDim.x + threadIdx.x;
    if (e >= n_edges) return;
    eoff[e] = atomicAdd(&counts[adj_row[e]], 1);
}

// ---- device-wide exclusive scan: 3 small kernels ----

// Each block scans its 1024-chunk (exclusive) and emits the chunk total.
__global__ void __launch_bounds__(1024) scan_block_kernel(
    const int* __restrict__ counts, int* __restrict__ row_ptr,
    int* __restrict__ partials)
{
    __shared__ int warp_sums[32];
    const int tid  = threadIdx.x;
    const int lane = tid & 31;
    const int wid  = tid >> 5;
    const int i    = blockIdx.x * SCAN_CHUNK + tid;

    int v = (i < N_NODES) ? counts[i] : 0;

    int incl = v;
    #pragma unroll
    for (int off = 1; off < 32; off <<= 1) {
        int t = __shfl_up_sync(0xffffffffu, incl, off);
        if (lane >= off) incl += t;
    }
    if (lane == 31) warp_sums[wid] = incl;
    __syncthreads();

    if (wid == 0) {
        int s = warp_sums[lane];
        int si = s;
        #pragma unroll
        for (int off = 1; off < 32; off <<= 1) {
            int t = __shfl_up_sync(0xffffffffu, si, off);
            if (lane >= off) si += t;
        }
        warp_sums[lane] = si - s;   // exclusive across warps
    }
    __syncthreads();

    int excl = incl - v + warp_sums[wid];
    if (i < N_NODES) row_ptr[i] = excl;
    if (tid == SCAN_CHUNK - 1) partials[blockIdx.x] = excl + v;
}

// One warp-sized block scans the SCAN_BLOCKS partial sums (exclusive).
__global__ void scan_partials_kernel(const int* __restrict__ partials,
                                     int* __restrict__ poffs,
                                     int* __restrict__ row_ptr)
{
    __shared__ int warp_sums[2];
    const int tid  = threadIdx.x;    // 64 threads
    const int lane = tid & 31;
    const int wid  = tid >> 5;

    int v = (tid < SCAN_BLOCKS) ? partials[tid] : 0;
    int incl = v;
    #pragma unroll
    for (int off = 1; off < 32; off <<= 1) {
        int t = __shfl_up_sync(0xffffffffu, incl, off);
        if (lane >= off) incl += t;
    }
    if (lane == 31) warp_sums[wid] = incl;
    __syncthreads();
    int wadd = (wid == 1) ? warp_sums[0] : 0;
    int excl = incl - v + wadd;
    if (tid < SCAN_BLOCKS) poffs[tid] = excl;
    if (tid == 63) row_ptr[N_NODES] = excl + v;   // grand total
}

// Add each chunk's prefix offset.
__global__ void __launch_bounds__(1024) add_offsets_kernel(
    int* __restrict__ row_ptr, const int* __restrict__ poffs)
{
    int i = blockIdx.x * SCAN_CHUNK + threadIdx.x;
    if (i < N_NODES) row_ptr[i] += poffs[blockIdx.x];
}

// Place packed (col, val) at row_ptr[row] + rank. One 8B random write/edge.
__global__ void scatter_kernel(const int* __restrict__ adj_row,
                               const int* __restrict__ adj_col,
                               const float* __restrict__ adj_vals,
                               const int* __restrict__ row_ptr,
                               const int* __restrict__ eoff,
                               int2* __restrict__ edges,
                               int n_edges) {
    int e = blockIdx.x * blockDim.x + threadIdx.x;
    if (e >= n_edges) return;
    int r = adj_row[e];
    int p = row_ptr[r] + eoff[e];
    float v = adj_vals[e];
    edges[p] = make_int2(adj_col[e], __float_as_int(v));
}

// ---------------- CSR SpMM: warp/row, fp16 gather, fp32 accumulate ----------
template <int OUT_HALF>
__global__ void __launch_bounds__(256) spmm_csr_h_kernel(
    const uint2* __restrict__ xh,
    const int*   __restrict__ row_ptr,
    const int2*  __restrict__ edges,
    void*        __restrict__ out)
{
    int row  = (blockIdx.x * blockDim.x + threadIdx.x) >> 5;
    int lane = threadIdx.x & 31;
    if (row >= N_NODES) return;

    int start = row_ptr[row];
    int end   = row_ptr[row + 1];

    float4 acc = make_float4(0.f, 0.f, 0.f, 0.f);

    for (int base = start; base < end; base += 32) {
        int n = end - base;
        if (n > 32) n = 32;
        int2 ep = make_int2(0, 0);
        if (lane < n) ep = __ldg(edges + base + lane);

        #pragma unroll 8
        for (int j = 0; j < n; j++) {
            int   cj = __shfl_sync(0xffffffffu, ep.x, j);
            int   vb = __shfl_sync(0xffffffffu, ep.y, j);
            float vj = __int_as_float(vb);
            uint2 m  = __ldg(xh + (size_t)cj * NH2 + lane);
            __half2 h0 = *reinterpret_cast<__half2*>(&m.x);
            __half2 h1 = *reinterpret_cast<__half2*>(&m.y);
            float2 f0 = __half22float2(h0);
            float2 f1 = __half22float2(h1);
            acc.x = fmaf(vj, f0.x, acc.x);
            acc.y = fmaf(vj, f0.y, acc.y);
            acc.z = fmaf(vj, f1.x, acc.z);
            acc.w = fmaf(vj, f1.y, acc.w);
        }
    }

    if (OUT_HALF) {
        __half2 h0 = __float22half2_rn(make_float2(acc.x, acc.y));
        __half2 h1 = __float22half2_rn(make_float2(acc.z, acc.w));
        uint2 o;
        o.x = *reinterpret_cast<unsigned*>(&h0);
        o.y = *reinterpret_cast<unsigned*>(&h1);
        reinterpret_cast<uint2*>(out)[(size_t)row * NH2 + lane] = o;
    } else {
        reinterpret_cast<float4*>(out)[(size_t)row * NV4 + lane] = acc;
    }
}

// ---------------- launch ----------------
extern "C" void kernel_launch(void* const* d_in, const int* in_sizes, int n_in,
                              void* d_out, int out_size) {
    const float* x        = (const float*)d_in[0];
    const int*   adj_row  = (const int*)  d_in[1];
    const int*   adj_col  = (const int*)  d_in[2];
    const float* adj_vals = (const float*)d_in[3];
    float*       out      = (float*)d_out;

    int n_edges = in_sizes[1];

    uint2 *xh, *scratchh; int *counts, *row_ptr, *eoff, *partials, *poffs; int2 *edges;
    cudaGetSymbolAddress((void**)&xh,       g_xh);
    cudaGetSymbolAddress((void**)&scratchh, g_scratchh);
    cudaGetSymbolAddress((void**)&counts,   g_counts);
    cudaGetSymbolAddress((void**)&row_ptr,  g_row_ptr);
    cudaGetSymbolAddress((void**)&eoff,     g_eoff);
    cudaGetSymbolAddress((void**)&partials, g_partials);
    cudaGetSymbolAddress((void**)&poffs,    g_poffs);
    cudaGetSymbolAddress((void**)&edges,    g_edges);

    const int T = 256;

    // CSR build + fp16 conversion of x.
    zero_counts_kernel<<<(N_NODES + T - 1) / T, T>>>(counts);
    hist_kernel<<<(n_edges + T - 1) / T, T>>>(adj_row, counts, eoff, n_edges);
    const int nconv = N_NODES * NH2;
    conv_kernel<<<(nconv + T - 1) / T, T>>>((const float4*)x, xh, nconv);

    scan_block_kernel<<<SCAN_BLOCKS, SCAN_CHUNK>>>(counts, row_ptr, partials);
    scan_partials_kernel<<<1, 64>>>(partials, poffs, row_ptr);
    add_offsets_kernel<<<SCAN_BLOCKS, SCAN_CHUNK>>>(row_ptr, poffs);

    scatter_kernel<<<(n_edges + T - 1) / T, T>>>(adj_row, adj_col, adj_vals,
                                                 row_ptr, eoff, edges, n_edges);

    // Two propagation rounds.
    const int WPB = T / 32;
    const int sb = (N_NODES + WPB - 1) / WPB;
    spmm_csr_h_kernel<1><<<sb, T>>>(xh, row_ptr, edges, scratchh);
    spmm_csr_h_kernel<0><<<sb, T>>>(scratchh, row_ptr, edges, out);
}

// round 6
// speedup vs baseline: 1.3761x; 1.3761x over previous
#include <cuda_runtime.h>
#include <cuda_fp16.h>
#include <cstdint>

#define N_NODES 50000
#define N_EDGES 1600000
#define D_FEAT  128
#define NH4     (D_FEAT / 8)   // 16 uint4 (8 halfs) per fp16 row

#define SCAN_CHUNK   1024
#define SCAN_BLOCKS  ((N_NODES + SCAN_CHUNK - 1) / SCAN_CHUNK)   // 49

// Scratch (no cudaMalloc allowed).
__device__ uint4 g_xh      [(size_t)N_NODES * NH4];   // fp16 copy of gather operand
__device__ uint4 g_scratchh[(size_t)N_NODES * NH4];   // fp16 round-1 result
__device__ int   g_counts  [N_NODES];
__device__ int   g_row_ptr [N_NODES + 1];
__device__ int   g_eoff    [N_EDGES];
__device__ int2  g_edges   [N_EDGES];                 // packed (col, val-bits)
__device__ int   g_partials[SCAN_BLOCKS];
__device__ int   g_poffs   [SCAN_BLOCKS];

// ---------------- fp32 -> fp16 conversion (8 feats / thread) ----------------
__global__ void conv_kernel(const float4* __restrict__ in, uint4* __restrict__ out, int n) {
    int i = blockIdx.x * blockDim.x + threadIdx.x;
    if (i >= n) return;
    float4 f0 = in[2 * i];
    float4 f1 = in[2 * i + 1];
    __half2 h0 = __float22half2_rn(make_float2(f0.x, f0.y));
    __half2 h1 = __float22half2_rn(make_float2(f0.z, f0.w));
    __half2 h2 = __float22half2_rn(make_float2(f1.x, f1.y));
    __half2 h3 = __float22half2_rn(make_float2(f1.z, f1.w));
    uint4 o;
    o.x = *reinterpret_cast<unsigned*>(&h0);
    o.y = *reinterpret_cast<unsigned*>(&h1);
    o.z = *reinterpret_cast<unsigned*>(&h2);
    o.w = *reinterpret_cast<unsigned*>(&h3);
    out[i] = o;
}

// ---------------- CSR build ----------------
__global__ void zero_counts_kernel(int* __restrict__ counts) {
    int i = blockIdx.x * blockDim.x + threadIdx.x;
    if (i < N_NODES) counts[i] = 0;
}

__global__ void hist_kernel(const int* __restrict__ adj_row, int* __restrict__ counts,
                            int* __restrict__ eoff, int n_edges) {
    int e = blockIdx.x * blockDim.x + threadIdx.x;
    if (e >= n_edges) return;
    eoff[e] = atomicAdd(&counts[adj_row[e]], 1);
}

__global__ void __launch_bounds__(1024) scan_block_kernel(
    const int* __restrict__ counts, int* __restrict__ row_ptr,
    int* __restrict__ partials)
{
    __shared__ int warp_sums[32];
    const int tid  = threadIdx.x;
    const int lane = tid & 31;
    const int wid  = tid >> 5;
    const int i    = blockIdx.x * SCAN_CHUNK + tid;

    int v = (i < N_NODES) ? counts[i] : 0;

    int incl = v;
    #pragma unroll
    for (int off = 1; off < 32; off <<= 1) {
        int t = __shfl_up_sync(0xffffffffu, incl, off);
        if (lane >= off) incl += t;
    }
    if (lane == 31) warp_sums[wid] = incl;
    __syncthreads();

    if (wid == 0) {
        int s = warp_sums[lane];
        int si = s;
        #pragma unroll
        for (int off = 1; off < 32; off <<= 1) {
            int t = __shfl_up_sync(0xffffffffu, si, off);
            if (lane >= off) si += t;
        }
        warp_sums[lane] = si - s;
    }
    __syncthreads();

    int excl = incl - v + warp_sums[wid];
    if (i < N_NODES) row_ptr[i] = excl;
    if (tid == SCAN_CHUNK - 1) partials[blockIdx.x] = excl + v;
}

__global__ void scan_partials_kernel(const int* __restrict__ partials,
                                     int* __restrict__ poffs,
                                     int* __restrict__ row_ptr)
{
    __shared__ int warp_sums[2];
    const int tid  = threadIdx.x;    // 64 threads
    const int lane = tid & 31;
    const int wid  = tid >> 5;

    int v = (tid < SCAN_BLOCKS) ? partials[tid] : 0;
    int incl = v;
    #pragma unroll
    for (int off = 1; off < 32; off <<= 1) {
        int t = __shfl_up_sync(0xffffffffu, incl, off);
        if (lane >= off) incl += t;
    }
    if (lane == 31) warp_sums[wid] = incl;
    __syncthreads();
    int wadd = (wid == 1) ? warp_sums[0] : 0;
    int excl = incl - v + wadd;
    if (tid < SCAN_BLOCKS) poffs[tid] = excl;
    if (tid == 63) row_ptr[N_NODES] = excl + v;
}

__global__ void __launch_bounds__(1024) add_offsets_kernel(
    int* __restrict__ row_ptr, const int* __restrict__ poffs)
{
    int i = blockIdx.x * SCAN_CHUNK + threadIdx.x;
    if (i < N_NODES) row_ptr[i] += poffs[blockIdx.x];
}

__global__ void scatter_kernel(const int* __restrict__ adj_row,
                               const int* __restrict__ adj_col,
                               const float* __restrict__ adj_vals,
                               const int* __restrict__ row_ptr,
                               const int* __restrict__ eoff,
                               int2* __restrict__ edges,
                               int n_edges) {
    int e = blockIdx.x * blockDim.x + threadIdx.x;
    if (e >= n_edges) return;
    int r = adj_row[e];
    int p = row_ptr[r] + eoff[e];
    edges[p] = make_int2(adj_col[e], __float_as_int(adj_vals[e]));
}

// ---------------- CSR SpMM: warp/row, half-warp/edge, fp16 gather ------------
// Each half-warp (16 lanes x uint4 = 256B) covers the full fp16 feature row of
// one edge; a warp processes 2 edges per step. Final cross-half combine via
// shfl_xor(16). OUT_HALF=1: store fp16; else fp32.
template <int OUT_HALF>
__global__ void __launch_bounds__(256) spmm_csr_h_kernel(
    const uint4* __restrict__ xh,
    const int*   __restrict__ row_ptr,
    const int2*  __restrict__ edges,
    void*        __restrict__ out)
{
    int row  = (blockIdx.x * blockDim.x + threadIdx.x) >> 5;
    int lane = threadIdx.x & 31;
    if (row >= N_NODES) return;

    const int hlane = lane & 15;        // lane within half-warp
    const int half  = lane >> 4;        // 0 or 1

    int start = row_ptr[row];
    int end   = row_ptr[row + 1];

    float acc[8] = {0.f, 0.f, 0.f, 0.f, 0.f, 0.f, 0.f, 0.f};

    for (int base = start; base < end; base += 32) {
        int n = end - base;
        if (n > 32) n = 32;
        int2 ep = make_int2(0, 0);
        if (lane < n) ep = __ldg(edges + base + lane);

        #pragma unroll 4
        for (int j = 0; j < n; j += 2) {
            int je = j + half;
            int cj = __shfl_sync(0xffffffffu, ep.x, je);
            int vb = __shfl_sync(0xffffffffu, ep.y, je);
            if (je >= n) { cj = 0; vb = 0; }      // harmless zero-weight read of row 0
            float vj = __int_as_float(vb);

            uint4 m = __ldg(xh + (size_t)cj * NH4 + hlane);
            __half2 h0 = *reinterpret_cast<__half2*>(&m.x);
            __half2 h1 = *reinterpret_cast<__half2*>(&m.y);
            __half2 h2 = *reinterpret_cast<__half2*>(&m.z);
            __half2 h3 = *reinterpret_cast<__half2*>(&m.w);
            float2 f0 = __half22float2(h0);
            float2 f1 = __half22float2(h1);
            float2 f2 = __half22float2(h2);
            float2 f3 = __half22float2(h3);
            acc[0] = fmaf(vj, f0.x, acc[0]);
            acc[1] = fmaf(vj, f0.y, acc[1]);
            acc[2] = fmaf(vj, f1.x, acc[2]);
            acc[3] = fmaf(vj, f1.y, acc[3]);
            acc[4] = fmaf(vj, f2.x, acc[4]);
            acc[5] = fmaf(vj, f2.y, acc[5]);
            acc[6] = fmaf(vj, f3.x, acc[6]);
            acc[7] = fmaf(vj, f3.y, acc[7]);
        }
    }

    // Combine the two half-warps' partial sums (same feature positions).
    #pragma unroll
    for (int k = 0; k < 8; k++)
        acc[k] += __shfl_xor_sync(0xffffffffu, acc[k], 16);

    if (half == 0) {
        if (OUT_HALF) {
            __half2 h0 = __float22half2_rn(make_float2(acc[0], acc[1]));
            __half2 h1 = __float22half2_rn(make_float2(acc[2], acc[3]));
            __half2 h2 = __float22half2_rn(make_float2(acc[4], acc[5]));
            __half2 h3 = __float22half2_rn(make_float2(acc[6], acc[7]));
            uint4 o;
            o.x = *reinterpret_cast<unsigned*>(&h0);
            o.y = *reinterpret_cast<unsigned*>(&h1);
            o.z = *reinterpret_cast<unsigned*>(&h2);
            o.w = *reinterpret_cast<unsigned*>(&h3);
            reinterpret_cast<uint4*>(out)[(size_t)row * NH4 + hlane] = o;
        } else {
            float4* o4 = reinterpret_cast<float4*>(out) + (size_t)row * (D_FEAT / 4) + hlane * 2;
            o4[0] = make_float4(acc[0], acc[1], acc[2], acc[3]);
            o4[1] = make_float4(acc[4], acc[5], acc[6], acc[7]);
        }
    }
}

// ---------------- launch ----------------
extern "C" void kernel_launch(void* const* d_in, const int* in_sizes, int n_in,
                              void* d_out, int out_size) {
    const float* x        = (const float*)d_in[0];
    const int*   adj_row  = (const int*)  d_in[1];
    const int*   adj_col  = (const int*)  d_in[2];
    const float* adj_vals = (const float*)d_in[3];
    float*       out      = (float*)d_out;

    int n_edges = in_sizes[1];

    uint4 *xh, *scratchh; int *counts, *row_ptr, *eoff, *partials, *poffs; int2 *edges;
    cudaGetSymbolAddress((void**)&xh,       g_xh);
    cudaGetSymbolAddress((void**)&scratchh, g_scratchh);
    cudaGetSymbolAddress((void**)&counts,   g_counts);
    cudaGetSymbolAddress((void**)&row_ptr,  g_row_ptr);
    cudaGetSymbolAddress((void**)&eoff,     g_eoff);
    cudaGetSymbolAddress((void**)&partials, g_partials);
    cudaGetSymbolAddress((void**)&poffs,    g_poffs);
    cudaGetSymbolAddress((void**)&edges,    g_edges);

    const int T = 256;

    // CSR build + fp16 conversion of x.
    zero_counts_kernel<<<(N_NODES + T - 1) / T, T>>>(counts);
    hist_kernel<<<(n_edges + T - 1) / T, T>>>(adj_row, counts, eoff, n_edges);
    const int nconv = N_NODES * NH4;
    conv_kernel<<<(nconv + T - 1) / T, T>>>((const float4*)x, xh, nconv);

    scan_block_kernel<<<SCAN_BLOCKS, SCAN_CHUNK>>>(counts, row_ptr, partials);
    scan_partials_kernel<<<1, 64>>>(partials, poffs, row_ptr);
    add_offsets_kernel<<<SCAN_BLOCKS, SCAN_CHUNK>>>(row_ptr, poffs);

    scatter_kernel<<<(n_edges + T - 1) / T, T>>>(adj_row, adj_col, adj_vals,
                                                 row_ptr, eoff, edges, n_edges);

    // Two propagation rounds.
    const int WPB = T / 32;
    const int sb = (N_NODES + WPB - 1) / WPB;
    spmm_csr_h_kernel<1><<<sb, T>>>(xh, row_ptr, edges, scratchh);
    spmm_csr_h_kernel<0><<<sb, T>>>(scratchh, row_ptr, edges, out);
}